// round 6
// baseline (speedup 1.0000x reference)
#include <cuda_runtime.h>
#include <math.h>

// Problem dims (fixed per reference setup_inputs)
#define TT   4
#define BBB  64
#define NNN  256
#define DIN  512
#define DOUT 512
#define MROWS (TT * BBB * NNN)        // 65536 rows total
#define M3   (BBB * NNN * DOUT)       // 8388608 elems per time step
#define RED_ROWS 256
#define RED_BLOCKS (MROWS / RED_ROWS) // 256
#define BK 16
#define NCHUNKS (DIN / BK)            // 32

typedef unsigned long long u64;

// Scratch (allocation-free: __device__ globals)
__device__ float g_z[(size_t)MROWS * DOUT];
__device__ float g_psum[RED_BLOCKS * DOUT];
__device__ float g_psumsq[RED_BLOCKS * DOUT];
__device__ float g_mean[DOUT];
__device__ float g_rstd[DOUT];

__device__ __forceinline__ u64 pack2(float lo, float hi) {
    u64 r;
    asm("mov.b64 %0, {%1, %2};" : "=l"(r) : "f"(lo), "f"(hi));
    return r;
}
__device__ __forceinline__ float2 unpack2(u64 v) {
    float lo, hi;
    asm("mov.b64 {%0, %1}, %2;" : "=f"(lo), "=f"(hi) : "l"(v));
    return make_float2(lo, hi);
}
// Packed pair of independent rn-rounded fp32 FMAs (Blackwell FFMA2).
__device__ __forceinline__ void ffma2(u64& c, u64 a, u64 b) {
    asm("fma.rn.f32x2 %0, %1, %2, %0;" : "+l"(c) : "l"(a), "l"(b));
}

// ---------------------------------------------------------------------------
// SGEMM: Z[m,o] = sum_d X[m,d] * W[o,d]
// 128x128 CTA tile, BK=16, 256 threads, 8x8 per thread, double-buffered SMEM.
// Inner product evaluated with fma.rn.f32x2 pairing adjacent ROWS; each
// acc[i][j] remains a single fp32 rn chain over k = 0..511 ascending ->
// bit-identical to the round-1/round-4 passing kernels.
// ---------------------------------------------------------------------------
__global__ __launch_bounds__(256, 2) void sgemm_kernel(const float* __restrict__ X,
                                                       const float* __restrict__ W) {
    __shared__ __align__(16) float As[2][BK][128];
    __shared__ __align__(16) float Bs[2][BK][128];

    const int tid = threadIdx.x;
    const int tx = tid & 15;          // column groups
    const int ty = tid >> 4;          // row groups
    const int r0 = tid >> 2;          // load row (first half)
    const int q0 = tid & 3;           // float4 index within 16-float row chunk

    const float* Ab = X + (size_t)blockIdx.y * 128 * DIN;
    const float* Wb = W + (size_t)blockIdx.x * 128 * DIN;

    // c2[p][j]: packed pair (acc[row even], acc[row odd]) for col j
    u64 c2[4][8];
    const u64 zz = pack2(0.f, 0.f);
#pragma unroll
    for (int p = 0; p < 4; p++)
#pragma unroll
        for (int j = 0; j < 8; j++) c2[p][j] = zz;

    float4 ra0, ra1, rb0, rb1;

    // --- prologue: chunk 0 -> buf 0
    ra0 = *reinterpret_cast<const float4*>(Ab + (size_t)r0 * DIN + q0 * 4);
    ra1 = *reinterpret_cast<const float4*>(Ab + (size_t)(r0 + 64) * DIN + q0 * 4);
    rb0 = *reinterpret_cast<const float4*>(Wb + (size_t)r0 * DIN + q0 * 4);
    rb1 = *reinterpret_cast<const float4*>(Wb + (size_t)(r0 + 64) * DIN + q0 * 4);
    {
        float a0[4] = {ra0.x, ra0.y, ra0.z, ra0.w};
        float a1[4] = {ra1.x, ra1.y, ra1.z, ra1.w};
        float b0[4] = {rb0.x, rb0.y, rb0.z, rb0.w};
        float b1[4] = {rb1.x, rb1.y, rb1.z, rb1.w};
#pragma unroll
        for (int u = 0; u < 4; u++) {
            As[0][q0 * 4 + u][r0]      = a0[u];
            As[0][q0 * 4 + u][r0 + 64] = a1[u];
            Bs[0][q0 * 4 + u][r0]      = b0[u];
            Bs[0][q0 * 4 + u][r0 + 64] = b1[u];
        }
    }
    __syncthreads();

    // LDG chunk 1
    ra0 = *reinterpret_cast<const float4*>(Ab + (size_t)r0 * DIN + BK + q0 * 4);
    ra1 = *reinterpret_cast<const float4*>(Ab + (size_t)(r0 + 64) * DIN + BK + q0 * 4);
    rb0 = *reinterpret_cast<const float4*>(Wb + (size_t)r0 * DIN + BK + q0 * 4);
    rb1 = *reinterpret_cast<const float4*>(Wb + (size_t)(r0 + 64) * DIN + BK + q0 * 4);

    for (int c = 0; c < NCHUNKS; c++) {
        const int cur = c & 1;
        if (c + 1 < NCHUNKS) {
            const int nxt = cur ^ 1;
            float a0[4] = {ra0.x, ra0.y, ra0.z, ra0.w};
            float a1[4] = {ra1.x, ra1.y, ra1.z, ra1.w};
            float b0[4] = {rb0.x, rb0.y, rb0.z, rb0.w};
            float b1[4] = {rb1.x, rb1.y, rb1.z, rb1.w};
#pragma unroll
            for (int u = 0; u < 4; u++) {
                As[nxt][q0 * 4 + u][r0]      = a0[u];
                As[nxt][q0 * 4 + u][r0 + 64] = a1[u];
                Bs[nxt][q0 * 4 + u][r0]      = b0[u];
                Bs[nxt][q0 * 4 + u][r0 + 64] = b1[u];
            }
        }
        if (c + 2 < NCHUNKS) {
            const int k0 = (c + 2) * BK;
            ra0 = *reinterpret_cast<const float4*>(Ab + (size_t)r0 * DIN + k0 + q0 * 4);
            ra1 = *reinterpret_cast<const float4*>(Ab + (size_t)(r0 + 64) * DIN + k0 + q0 * 4);
            rb0 = *reinterpret_cast<const float4*>(Wb + (size_t)r0 * DIN + k0 + q0 * 4);
            rb1 = *reinterpret_cast<const float4*>(Wb + (size_t)(r0 + 64) * DIN + k0 + q0 * 4);
        }
        // Compute chunk c: k ascending; row-paired FFMA2
#pragma unroll
        for (int kk = 0; kk < BK; kk++) {
            float4 a0 = *reinterpret_cast<const float4*>(&As[cur][kk][ty * 4]);
            float4 a1 = *reinterpret_cast<const float4*>(&As[cur][kk][64 + ty * 4]);
            float4 b0 = *reinterpret_cast<const float4*>(&Bs[cur][kk][tx * 4]);
            float4 b1 = *reinterpret_cast<const float4*>(&Bs[cur][kk][64 + tx * 4]);
            u64 a2[4];
            a2[0] = pack2(a0.x, a0.y); a2[1] = pack2(a0.z, a0.w);
            a2[2] = pack2(a1.x, a1.y); a2[3] = pack2(a1.z, a1.w);
            float rb[8] = {b0.x, b0.y, b0.z, b0.w, b1.x, b1.y, b1.z, b1.w};
            u64 b2[8];
#pragma unroll
            for (int j = 0; j < 8; j++) b2[j] = pack2(rb[j], rb[j]);
#pragma unroll
            for (int p = 0; p < 4; p++)
#pragma unroll
                for (int j = 0; j < 8; j++) ffma2(c2[p][j], a2[p], b2[j]);
        }
        __syncthreads();
    }

    // Epilogue: p -> row pair {(p>>1)*64 + ty*4 + (p&1)*2, +1}; j -> col as before
#pragma unroll
    for (int p = 0; p < 4; p++) {
        int rbase = blockIdx.y * 128 + (p >> 1) * 64 + ty * 4 + (p & 1) * 2;
        float* z0 = g_z + (size_t)rbase * DOUT + blockIdx.x * 128;
        float* z1 = z0 + DOUT;
#pragma unroll
        for (int ch = 0; ch < 2; ch++) {
            float2 u0 = unpack2(c2[p][ch * 4 + 0]);
            float2 u1 = unpack2(c2[p][ch * 4 + 1]);
            float2 u2 = unpack2(c2[p][ch * 4 + 2]);
            float2 u3 = unpack2(c2[p][ch * 4 + 3]);
            float4 vlo = make_float4(u0.x, u1.x, u2.x, u3.x);
            float4 vhi = make_float4(u0.y, u1.y, u2.y, u3.y);
            *reinterpret_cast<float4*>(z0 + ch * 64 + tx * 4) = vlo;
            *reinterpret_cast<float4*>(z1 + ch * 64 + tx * 4) = vhi;
        }
    }
}

// ---------------------------------------------------------------------------
// Stats + LIF: verbatim from the round-1 PASSING kernel.
// ---------------------------------------------------------------------------
__global__ __launch_bounds__(256) void reduce_stats_kernel() {
    const int c = threadIdx.x;
    const size_t base = (size_t)blockIdx.x * RED_ROWS * DOUT;
    float s0 = 0.f, q0 = 0.f, s1 = 0.f, q1 = 0.f;
    for (int r = 0; r < RED_ROWS; r++) {
        float z0 = g_z[base + (size_t)r * DOUT + c];
        float z1 = g_z[base + (size_t)r * DOUT + c + 256];
        s0 += z0; q0 += z0 * z0;
        s1 += z1; q1 += z1 * z1;
    }
    g_psum  [blockIdx.x * DOUT + c]       = s0;
    g_psumsq[blockIdx.x * DOUT + c]       = q0;
    g_psum  [blockIdx.x * DOUT + c + 256] = s1;
    g_psumsq[blockIdx.x * DOUT + c + 256] = q1;
}

__global__ void finalize_stats_kernel() {
    const int o = threadIdx.x;
    float s = 0.f, q = 0.f;
    for (int b = 0; b < RED_BLOCKS; b++) {
        s += g_psum[b * DOUT + o];
        q += g_psumsq[b * DOUT + o];
    }
    const float invM = 1.0f / (float)MROWS;
    float mean = s * invM;
    float var = q * invM - mean * mean;
    g_mean[o] = mean;
    g_rstd[o] = 1.0f / sqrtf(var + 1e-5f);
}

__global__ __launch_bounds__(256) void lif_kernel(const float* __restrict__ gamma,
                                                  const float* __restrict__ beta,
                                                  float* __restrict__ out) {
    size_t e = ((size_t)blockIdx.x * blockDim.x + threadIdx.x) * 4;
    int o = (int)(e & (DOUT - 1));

    float4 mn4 = *reinterpret_cast<const float4*>(g_mean + o);
    float4 rs4 = *reinterpret_cast<const float4*>(g_rstd + o);
    float4 gm4 = *reinterpret_cast<const float4*>(gamma + o);
    float4 bt4 = *reinterpret_cast<const float4*>(beta + o);
    float mn[4] = {mn4.x, mn4.y, mn4.z, mn4.w};
    float rs[4] = {rs4.x, rs4.y, rs4.z, rs4.w};
    float gm[4] = {gm4.x, gm4.y, gm4.z, gm4.w};
    float bt[4] = {bt4.x, bt4.y, bt4.z, bt4.w};

    float v[4] = {0.f, 0.f, 0.f, 0.f};
#pragma unroll
    for (int t = 0; t < TT; t++) {
        float4 z4 = *reinterpret_cast<const float4*>(g_z + (size_t)t * M3 + e);
        float z[4] = {z4.x, z4.y, z4.z, z4.w};
        float s[4];
#pragma unroll
        for (int l = 0; l < 4; l++) {
            float zn = __fadd_rn(__fmul_rn(__fmul_rn(__fsub_rn(z[l], mn[l]), rs[l]), gm[l]), bt[l]);
            v[l] = __fadd_rn(v[l], __fmul_rn(__fsub_rn(zn, v[l]), 0.5f));
            bool fire = (v[l] >= 1.0f);
            s[l] = fire ? 1.0f : 0.0f;
            v[l] = fire ? 0.0f : v[l];
        }
        *reinterpret_cast<float4*>(out + (size_t)t * M3 + e) = make_float4(s[0], s[1], s[2], s[3]);
    }
}

// ---------------------------------------------------------------------------
extern "C" void kernel_launch(void* const* d_in, const int* in_sizes, int n_in,
                              void* d_out, int out_size) {
    const float* x     = (const float*)d_in[0];
    const float* W     = (const float*)d_in[1];
    const float* gamma = (const float*)d_in[2];
    const float* beta  = (const float*)d_in[3];
    float* out = (float*)d_out;

    dim3 gemm_grid(DOUT / 128, MROWS / 128);     // (4, 512)
    sgemm_kernel<<<gemm_grid, 256>>>(x, W);
    reduce_stats_kernel<<<RED_BLOCKS, 256>>>();
    finalize_stats_kernel<<<1, DOUT>>>();
    lif_kernel<<<M3 / (256 * 4), 256>>>(gamma, beta, out);
}